// round 1
// baseline (speedup 1.0000x reference)
#include <cuda_runtime.h>
#include <cuda_bf16.h>
#include <math.h>
#include <stdint.h>

// Problem constants
#define NN      16384     // nodes
#define MMN     32        // neighbors
#define FF      256       // features (in == out)
#define ALPHA_L 0.2f      // leaky relu slope

// Tiling
#define ROWS_PB   128     // rows per block (4 nodes * 32 neighbors)
#define NODES_PB  4
#define THREADS   256     // 8 warps
#define A_STRIDE  260     // padded row stride for A tile (conflict-free frags)
#define W_STRIDE  72      // padded row stride for W chunk (conflict-free frags)
#define NCHUNK    64      // output-feature chunk width
#define NCHUNKS   (FF / NCHUNK)

// Scratch: O2 = output @ W2  (bias term, per node per out-feature)
__device__ float g_O2[(size_t)NN * FF];

__device__ __forceinline__ uint32_t f2tf32(float x) {
    uint32_t r;
    asm("cvt.rna.tf32.f32 %0, %1;" : "=r"(r) : "f"(x));
    return r;
}

__device__ __forceinline__ void mma_tf32(float c[4],
                                         uint32_t a0, uint32_t a1, uint32_t a2, uint32_t a3,
                                         uint32_t b0, uint32_t b1) {
    asm volatile(
        "mma.sync.aligned.m16n8k8.row.col.f32.tf32.tf32.f32 "
        "{%0,%1,%2,%3}, {%4,%5,%6,%7}, {%8,%9}, {%0,%1,%2,%3};\n"
        : "+f"(c[0]), "+f"(c[1]), "+f"(c[2]), "+f"(c[3])
        : "r"(a0), "r"(a1), "r"(a2), "r"(a3), "r"(b0), "r"(b1));
}

// ---------------------------------------------------------------------------
// Kernel 1: O2[r, o] = sum_k output[r, k] * W[256 + k, o]
// grid = NN/128 blocks, 256 threads.
// smem: As[128][A_STRIDE] (tf32-converted), Ws[256][W_STRIDE]
// ---------------------------------------------------------------------------
__global__ void __launch_bounds__(THREADS, 1)
o2_gemm_kernel(const float* __restrict__ output, const float* __restrict__ W) {
    extern __shared__ float smem[];
    float* As = smem;                      // 128 * 260
    float* Ws = As + ROWS_PB * A_STRIDE;   // 256 * 72

    const int tid  = threadIdx.x;
    const int w    = tid >> 5;
    const int lane = tid & 31;
    const int g    = lane >> 2;
    const int tg   = lane & 3;
    const int mbase = w * 16;
    const int row0 = blockIdx.x * ROWS_PB;

    // Load A tile (output rows), converting to tf32 at store.
    for (int idx = tid; idx < ROWS_PB * (FF / 4); idx += THREADS) {
        int r  = idx >> 6;
        int c4 = (idx & 63) * 4;
        float4 v = *(const float4*)(output + (size_t)(row0 + r) * FF + c4);
        float* d = &As[r * A_STRIDE + c4];
        d[0] = __uint_as_float(f2tf32(v.x));
        d[1] = __uint_as_float(f2tf32(v.y));
        d[2] = __uint_as_float(f2tf32(v.z));
        d[3] = __uint_as_float(f2tf32(v.w));
    }

    for (int nc = 0; nc < NCHUNKS; nc++) {
        __syncthreads();
        // Load W2 chunk: W[(256+k), nc*64 + j], tf32
        for (int idx = tid; idx < FF * (NCHUNK / 4); idx += THREADS) {
            int k = idx >> 4;
            int j = (idx & 15) * 4;
            float4 v = *(const float4*)(W + (size_t)(FF + k) * FF + nc * NCHUNK + j);
            float* d = &Ws[k * W_STRIDE + j];
            d[0] = __uint_as_float(f2tf32(v.x));
            d[1] = __uint_as_float(f2tf32(v.y));
            d[2] = __uint_as_float(f2tf32(v.z));
            d[3] = __uint_as_float(f2tf32(v.w));
        }
        __syncthreads();

        float c[8][4];
        #pragma unroll
        for (int n0 = 0; n0 < 8; n0++)
            #pragma unroll
            for (int i = 0; i < 4; i++) c[n0][i] = 0.f;

        #pragma unroll 4
        for (int k0 = 0; k0 < FF; k0 += 8) {
            uint32_t a0 = __float_as_uint(As[(mbase + g)     * A_STRIDE + k0 + tg]);
            uint32_t a1 = __float_as_uint(As[(mbase + g + 8) * A_STRIDE + k0 + tg]);
            uint32_t a2 = __float_as_uint(As[(mbase + g)     * A_STRIDE + k0 + tg + 4]);
            uint32_t a3 = __float_as_uint(As[(mbase + g + 8) * A_STRIDE + k0 + tg + 4]);
            #pragma unroll
            for (int n0 = 0; n0 < 8; n0++) {
                uint32_t b0 = __float_as_uint(Ws[(k0 + tg)     * W_STRIDE + n0 * 8 + g]);
                uint32_t b1 = __float_as_uint(Ws[(k0 + tg + 4) * W_STRIDE + n0 * 8 + g]);
                mma_tf32(c[n0], a0, a1, a2, a3, b0, b1);
            }
        }

        #pragma unroll
        for (int n0 = 0; n0 < 8; n0++) {
            int col = nc * NCHUNK + n0 * 8 + tg * 2;
            size_t rA = (size_t)(row0 + mbase + g) * FF + col;
            size_t rB = (size_t)(row0 + mbase + g + 8) * FF + col;
            g_O2[rA]     = c[n0][0];
            g_O2[rA + 1] = c[n0][1];
            g_O2[rB]     = c[n0][2];
            g_O2[rB + 1] = c[n0][3];
        }
    }
}

// ---------------------------------------------------------------------------
// Kernel 2: fused GAT per 4 nodes.
//  - A tile = transformed[4 nodes][32][256] in smem (fp32, read ONCE from HBM)
//  - e[row] = sum_o lrelu( (A@W1)[row,o] + O2[node,o] ) * a[o]
//  - softmax over 32 neighbors, write attention
//  - h_prime = sum_m att*A  (from smem), elu, write
// ---------------------------------------------------------------------------
__global__ void __launch_bounds__(THREADS, 1)
gat_fused_kernel(const float* __restrict__ transformed,
                 const float* __restrict__ W,
                 const float* __restrict__ a_vec,
                 float* __restrict__ out) {
    extern __shared__ float smem[];
    float* As    = smem;                          // 128 * 260 (fp32!)
    float* Ws    = As + ROWS_PB * A_STRIDE;       // 256 * 72 (tf32)
    float* a_s   = Ws + FF * W_STRIDE;            // 256
    float* o2_s  = a_s + FF;                      // 256 (4 nodes x 64)
    float* e_s   = o2_s + NODES_PB * NCHUNK;      // 128
    float* att_s = e_s + ROWS_PB;                 // 128

    const int tid  = threadIdx.x;
    const int w    = tid >> 5;
    const int lane = tid & 31;
    const int g    = lane >> 2;
    const int tg   = lane & 3;
    const int mbase  = w * 16;
    const int node_l = mbase >> 5;                // local node of this warp's rows
    const int node0  = blockIdx.x * NODES_PB;

    // Load A tile (transformed rows) in full fp32.
    for (int idx = tid; idx < ROWS_PB * (FF / 4); idx += THREADS) {
        int r  = idx >> 6;
        int c4 = (idx & 63) * 4;
        float4 v = *(const float4*)(transformed + (size_t)(node0 * MMN + r) * FF + c4);
        *(float4*)(&As[r * A_STRIDE + c4]) = v;
    }
    if (tid < FF)     a_s[tid] = a_vec[tid];
    if (tid < ROWS_PB) e_s[tid] = 0.f;

    for (int nc = 0; nc < NCHUNKS; nc++) {
        __syncthreads();
        // Load W1 chunk (tf32) + O2 bias chunk
        for (int idx = tid; idx < FF * (NCHUNK / 4); idx += THREADS) {
            int k = idx >> 4;
            int j = (idx & 15) * 4;
            float4 v = *(const float4*)(W + (size_t)k * FF + nc * NCHUNK + j);
            float* d = &Ws[k * W_STRIDE + j];
            d[0] = __uint_as_float(f2tf32(v.x));
            d[1] = __uint_as_float(f2tf32(v.y));
            d[2] = __uint_as_float(f2tf32(v.z));
            d[3] = __uint_as_float(f2tf32(v.w));
        }
        {
            int nl = tid >> 6;
            int j  = tid & 63;
            o2_s[tid] = g_O2[(size_t)(node0 + nl) * FF + nc * NCHUNK + j];
        }
        __syncthreads();

        float c[8][4];
        #pragma unroll
        for (int n0 = 0; n0 < 8; n0++)
            #pragma unroll
            for (int i = 0; i < 4; i++) c[n0][i] = 0.f;

        #pragma unroll 4
        for (int k0 = 0; k0 < FF; k0 += 8) {
            uint32_t a0 = f2tf32(As[(mbase + g)     * A_STRIDE + k0 + tg]);
            uint32_t a1 = f2tf32(As[(mbase + g + 8) * A_STRIDE + k0 + tg]);
            uint32_t a2 = f2tf32(As[(mbase + g)     * A_STRIDE + k0 + tg + 4]);
            uint32_t a3 = f2tf32(As[(mbase + g + 8) * A_STRIDE + k0 + tg + 4]);
            #pragma unroll
            for (int n0 = 0; n0 < 8; n0++) {
                uint32_t b0 = __float_as_uint(Ws[(k0 + tg)     * W_STRIDE + n0 * 8 + g]);
                uint32_t b1 = __float_as_uint(Ws[(k0 + tg + 4) * W_STRIDE + n0 * 8 + g]);
                mma_tf32(c[n0], a0, a1, a2, a3, b0, b1);
            }
        }

        // Epilogue: + O2 bias, leaky-relu, dot with a, accumulate e per row.
        float sumA = 0.f, sumB = 0.f;
        #pragma unroll
        for (int n0 = 0; n0 < 8; n0++) {
            int jj = n0 * 8 + tg * 2;
            float o20 = o2_s[node_l * NCHUNK + jj];
            float o21 = o2_s[node_l * NCHUNK + jj + 1];
            float av0 = a_s[nc * NCHUNK + jj];
            float av1 = a_s[nc * NCHUNK + jj + 1];
            float y;
            y = c[n0][0] + o20; y = (y > 0.f) ? y : ALPHA_L * y; sumA += y * av0;
            y = c[n0][1] + o21; y = (y > 0.f) ? y : ALPHA_L * y; sumA += y * av1;
            y = c[n0][2] + o20; y = (y > 0.f) ? y : ALPHA_L * y; sumB += y * av0;
            y = c[n0][3] + o21; y = (y > 0.f) ? y : ALPHA_L * y; sumB += y * av1;
        }
        // reduce across the 4-thread quad (same row)
        sumA += __shfl_down_sync(0xffffffffu, sumA, 2, 4);
        sumA += __shfl_down_sync(0xffffffffu, sumA, 1, 4);
        sumB += __shfl_down_sync(0xffffffffu, sumB, 2, 4);
        sumB += __shfl_down_sync(0xffffffffu, sumB, 1, 4);
        if (tg == 0) {
            e_s[mbase + g]     += sumA;
            e_s[mbase + 8 + g] += sumB;
        }
    }
    __syncthreads();

    // Softmax over neighbors: warp w (<4) handles node w.
    if (w < NODES_PB) {
        float v = e_s[w * MMN + lane];
        float mx = v;
        #pragma unroll
        for (int o = 16; o > 0; o >>= 1)
            mx = fmaxf(mx, __shfl_xor_sync(0xffffffffu, mx, o));
        float p = expf(v - mx);
        float s = p;
        #pragma unroll
        for (int o = 16; o > 0; o >>= 1)
            s += __shfl_xor_sync(0xffffffffu, s, o);
        float att = p / s;
        att_s[w * MMN + lane] = att;
        out[(size_t)NN * FF + (size_t)(node0 + w) * MMN + lane] = att;
    }
    __syncthreads();

    // h_prime[f] = sum_m att[m] * transformed[n, m, f], then ELU.
    #pragma unroll
    for (int nl = 0; nl < NODES_PB; nl++) {
        float acc = 0.f;
        #pragma unroll 8
        for (int m = 0; m < MMN; m++)
            acc = fmaf(att_s[nl * MMN + m], As[(nl * MMN + m) * A_STRIDE + tid], acc);
        float r = (acc > 0.f) ? acc : expm1f(acc);
        out[(size_t)(node0 + nl) * FF + tid] = r;
    }
}

// ---------------------------------------------------------------------------
extern "C" void kernel_launch(void* const* d_in, const int* in_sizes, int n_in,
                              void* d_out, int out_size) {
    const float* transformed = (const float*)d_in[0];  // [N, M, F]
    const float* output      = (const float*)d_in[1];  // [N, F]
    const float* W           = (const float*)d_in[2];  // [2F, F]
    const float* a_vec       = (const float*)d_in[3];  // [F, 1]
    float* out = (float*)d_out;

    const int smem_o2  = (ROWS_PB * A_STRIDE + FF * W_STRIDE) * sizeof(float);
    const int smem_gat = (ROWS_PB * A_STRIDE + FF * W_STRIDE + FF +
                          NODES_PB * NCHUNK + ROWS_PB + ROWS_PB) * sizeof(float);

    cudaFuncSetAttribute(o2_gemm_kernel,
                         cudaFuncAttributeMaxDynamicSharedMemorySize, smem_o2);
    cudaFuncSetAttribute(gat_fused_kernel,
                         cudaFuncAttributeMaxDynamicSharedMemorySize, smem_gat);

    o2_gemm_kernel<<<NN / ROWS_PB, THREADS, smem_o2>>>(output, W);
    gat_fused_kernel<<<NN / NODES_PB, THREADS, smem_gat>>>(transformed, W, a_vec, out);
}

// round 4
// speedup vs baseline: 1.1659x; 1.1659x over previous
#include <cuda_runtime.h>
#include <math.h>
#include <stdint.h>

// Problem constants
#define NN      16384
#define MMN     32
#define FF      256
#define ALPHA_L 0.2f

#define THREADS 256

// ---------------- scratch ----------------
__device__ float g_O2[(size_t)NN * FF];   // output @ W2 (bias per node per out-feat)
// W1 rearranged: 8 blocks [nc(4)][kh(2)] of [n_local(64)][k_local(128) interleaved]
__device__ float g_Wt[(size_t)FF * FF];

// ---------------- helpers ----------------
__device__ __forceinline__ uint32_t f2tf32(float x) {
    uint32_t r;
    asm("cvt.rna.tf32.f32 %0, %1;" : "=r"(r) : "f"(x));
    return r;
}

__device__ __forceinline__ uint32_t smem_to_u32(const void* p) {
    uint32_t a;
    asm("{ .reg .u64 t; cvta.to.shared.u64 t, %1; cvt.u32.u64 %0, t; }"
        : "=r"(a) : "l"(p));
    return a;
}

__device__ __forceinline__ void cp_async16(uint32_t dst_smem, const void* src) {
    asm volatile("cp.async.cg.shared.global [%0], [%1], 16;"
                 :: "r"(dst_smem), "l"(src) : "memory");
}
__device__ __forceinline__ void cp_async_commit() {
    asm volatile("cp.async.commit_group;" ::: "memory");
}
template <int N>
__device__ __forceinline__ void cp_async_wait() {
    asm volatile("cp.async.wait_group %0;" :: "n"(N) : "memory");
}

__device__ __forceinline__ void mma_tf32(float c[4],
                                         float a0, float a1, float a2, float a3,
                                         float b0, float b1) {
    asm volatile(
        "mma.sync.aligned.m16n8k8.row.col.f32.tf32.tf32.f32 "
        "{%0,%1,%2,%3}, {%4,%5,%6,%7}, {%8,%9}, {%0,%1,%2,%3};\n"
        : "+f"(c[0]), "+f"(c[1]), "+f"(c[2]), "+f"(c[3])
        : "r"(__float_as_uint(a0)), "r"(__float_as_uint(a1)),
          "r"(__float_as_uint(a2)), "r"(__float_as_uint(a3)),
          "r"(__float_as_uint(b0)), "r"(__float_as_uint(b1)));
}

// ---------------------------------------------------------------------------
// Kernel 0: W1 -> g_Wt, tf32-rounded, block-rearranged + k-pair interleaved
// block layout: blk = nc*2 + kh ; inside: row n_local (64), 128 k_local floats
// interleave within 8-block: k -> 2*(k&3) + ((k>>2)&1)
// ---------------------------------------------------------------------------
__global__ void wt_kernel(const float* __restrict__ W) {
    int n = blockIdx.x, k = threadIdx.x;
    int nc = n >> 6, nl = n & 63;
    int kh = k >> 7, kl = k & 127;
    int pos = (kl & ~7) + 2 * (kl & 3) + ((kl >> 2) & 1);
    size_t dst = ((size_t)((nc * 2 + kh) * 64 + nl)) * 128 + pos;
    g_Wt[dst] = __uint_as_float(f2tf32(W[(size_t)k * FF + n]));
}

// ---------------------------------------------------------------------------
// Kernel 1: O2 = output @ W2  (round-1 proven kernel, unchanged)
// ---------------------------------------------------------------------------
#define ROWS_PB   128
#define A_STRIDE1 260
#define W_STRIDE1 72

__global__ void __launch_bounds__(THREADS, 1)
o2_gemm_kernel(const float* __restrict__ output, const float* __restrict__ W) {
    extern __shared__ float smemf[];
    float* As = smemf;
    float* Ws = As + ROWS_PB * A_STRIDE1;

    const int tid  = threadIdx.x;
    const int w    = tid >> 5;
    const int lane = tid & 31;
    const int g    = lane >> 2;
    const int tg   = lane & 3;
    const int mbase = w * 16;
    const int row0 = blockIdx.x * ROWS_PB;

    for (int idx = tid; idx < ROWS_PB * (FF / 4); idx += THREADS) {
        int r  = idx >> 6;
        int c4 = (idx & 63) * 4;
        float4 v = *(const float4*)(output + (size_t)(row0 + r) * FF + c4);
        float* d = &As[r * A_STRIDE1 + c4];
        d[0] = __uint_as_float(f2tf32(v.x));
        d[1] = __uint_as_float(f2tf32(v.y));
        d[2] = __uint_as_float(f2tf32(v.z));
        d[3] = __uint_as_float(f2tf32(v.w));
    }

    for (int nc = 0; nc < 4; nc++) {
        __syncthreads();
        for (int idx = tid; idx < FF * 16; idx += THREADS) {
            int k = idx >> 4;
            int j = (idx & 15) * 4;
            float4 v = *(const float4*)(W + (size_t)(FF + k) * FF + nc * 64 + j);
            float* d = &Ws[k * W_STRIDE1 + j];
            d[0] = __uint_as_float(f2tf32(v.x));
            d[1] = __uint_as_float(f2tf32(v.y));
            d[2] = __uint_as_float(f2tf32(v.z));
            d[3] = __uint_as_float(f2tf32(v.w));
        }
        __syncthreads();

        float c[8][4];
        #pragma unroll
        for (int n0 = 0; n0 < 8; n0++)
            #pragma unroll
            for (int i = 0; i < 4; i++) c[n0][i] = 0.f;

        #pragma unroll 4
        for (int k0 = 0; k0 < FF; k0 += 8) {
            float a0 = As[(mbase + g)     * A_STRIDE1 + k0 + tg];
            float a1 = As[(mbase + g + 8) * A_STRIDE1 + k0 + tg];
            float a2 = As[(mbase + g)     * A_STRIDE1 + k0 + tg + 4];
            float a3 = As[(mbase + g + 8) * A_STRIDE1 + k0 + tg + 4];
            #pragma unroll
            for (int n0 = 0; n0 < 8; n0++) {
                float b0 = Ws[(k0 + tg)     * W_STRIDE1 + n0 * 8 + g];
                float b1 = Ws[(k0 + tg + 4) * W_STRIDE1 + n0 * 8 + g];
                mma_tf32(c[n0], a0, a1, a2, a3, b0, b1);
            }
        }

        #pragma unroll
        for (int n0 = 0; n0 < 8; n0++) {
            int col = nc * 64 + n0 * 8 + tg * 2;
            size_t rA = (size_t)(row0 + mbase + g) * FF + col;
            size_t rB = (size_t)(row0 + mbase + g + 8) * FF + col;
            g_O2[rA]     = c[n0][0];
            g_O2[rA + 1] = c[n0][1];
            g_O2[rB]     = c[n0][2];
            g_O2[rB + 1] = c[n0][3];
        }
    }
}

// ---------------------------------------------------------------------------
// Kernel 2: fused GAT. 4m x 2n warp grid, N-chunk = 64, K double-buffered.
//   A smem: 128 x 260 fp32 (tf32-rounded), plain layout
//   B smem: 2 buffers x (64 n-rows x 128 k, stride 136), k-pair interleaved
// ---------------------------------------------------------------------------
#define A_ST 260
#define B_ST 136
#define A_BYTES    (128 * A_ST * 4)     // 133120
#define BBUF_BYTES (64 * B_ST * 4)      // 34816
#define GAT_SMEM   (A_BYTES + 2 * BBUF_BYTES + 4 * FF * 4 + FF * 4 + 128 * 4 + 2 * 128 * 4)

__global__ void __launch_bounds__(THREADS, 1)
gat_fused2_kernel(const float* __restrict__ transformed,
                  const float* __restrict__ a_vec,
                  float* __restrict__ out) {
    extern __shared__ char smem[];
    float* As    = (float*)smem;                               // 128 x 260
    float* Bs0   = (float*)(smem + A_BYTES);                   // 64 x 136
    float* Bs1   = (float*)(smem + A_BYTES + BBUF_BYTES);
    float* o2_s  = (float*)(smem + A_BYTES + 2 * BBUF_BYTES);  // 4 x 256
    float* a_s   = o2_s + 4 * FF;                              // 256
    float* att_s = a_s + FF;                                   // 128
    float* e_sh  = att_s + 128;                                // 2 x 128

    const uint32_t b0_u = smem_to_u32(Bs0);
    const uint32_t b1_u = smem_to_u32(Bs1);

    const int tid  = threadIdx.x;
    const int w    = tid >> 5;
    const int lane = tid & 31;
    const int g    = lane >> 2;
    const int tg   = lane & 3;
    const int mw   = w & 3;        // m-warp: rows [mw*32, mw*32+32) -> node mw
    const int nh   = w >> 2;       // n-warp: cols [nh*32, nh*32+32) within chunk
    const int mbase = mw * 32;
    const int node0 = blockIdx.x * 4;

    // ---- prefetch B blocks 0 and 1 (chunk 0, both k-halves) ----
    #pragma unroll
    for (int blk = 0; blk < 2; blk++) {
        const char* src = (const char*)(g_Wt + (size_t)blk * 64 * 128);
        uint32_t dst = blk ? b1_u : b0_u;
        for (int idx = tid; idx < 64 * 32; idx += THREADS) {
            int r = idx >> 5, c16 = (idx & 31) * 16;
            cp_async16(dst + r * (B_ST * 4) + c16, src + r * 512 + c16);
        }
        cp_async_commit();
    }

    // ---- A tile fill: plain layout, tf32-rounded (round-1 proven) ----
    const float* Asrc = transformed + (size_t)(node0 * MMN) * FF;
    for (int idx = tid; idx < 128 * 64; idx += THREADS) {
        int r  = idx >> 6;
        int c4 = (idx & 63) * 4;
        float4 v = *(const float4*)(Asrc + (size_t)r * FF + c4);
        float* d = &As[r * A_ST + c4];
        d[0] = __uint_as_float(f2tf32(v.x));
        d[1] = __uint_as_float(f2tf32(v.y));
        d[2] = __uint_as_float(f2tf32(v.z));
        d[3] = __uint_as_float(f2tf32(v.w));
    }
    // ---- O2 bias + attention vector ----
    for (int idx = tid; idx < 4 * FF; idx += THREADS)
        o2_s[idx] = g_O2[(size_t)(node0 + (idx >> 8)) * FF + (idx & 255)];
    a_s[tid] = a_vec[tid];

    float ep[4] = {0.f, 0.f, 0.f, 0.f};   // e partials: rows mbase+{g,g+8,g+16,g+24}
    float c[2][4][4];

    for (int it = 0; it < 8; it++) {       // it = nc*2 + kh
        const int nc = it >> 1;
        const int kh = it & 1;

        if (it == 7) cp_async_wait<0>(); else cp_async_wait<1>();
        __syncthreads();

        const float* Bs = (it & 1) ? Bs1 : Bs0;

        if (kh == 0) {
            #pragma unroll
            for (int mt = 0; mt < 2; mt++)
                #pragma unroll
                for (int nt = 0; nt < 4; nt++)
                    #pragma unroll
                    for (int i = 0; i < 4; i++) c[mt][nt][i] = 0.f;
        }

        const int kbase = kh * 128;
        #pragma unroll 4
        for (int ko = 0; ko < 128; ko += 8) {
            const int k0 = kbase + ko;
            // A: 8 scalar LDS.32 (conflict-free, banks 4g+tg)
            float aA0 = As[(mbase + g)      * A_ST + k0 + tg];
            float aA4 = As[(mbase + g)      * A_ST + k0 + tg + 4];
            float aB0 = As[(mbase + g + 8)  * A_ST + k0 + tg];
            float aB4 = As[(mbase + g + 8)  * A_ST + k0 + tg + 4];
            float aC0 = As[(mbase + g + 16) * A_ST + k0 + tg];
            float aC4 = As[(mbase + g + 16) * A_ST + k0 + tg + 4];
            float aD0 = As[(mbase + g + 24) * A_ST + k0 + tg];
            float aD4 = As[(mbase + g + 24) * A_ST + k0 + tg + 4];
            // B: 4 x LDS.64, interleaved pairs (k, k+4) at float index ko + 2tg
            float2 b[4];
            #pragma unroll
            for (int nt = 0; nt < 4; nt++)
                b[nt] = *(const float2*)&Bs[(nh * 32 + nt * 8 + g) * B_ST + ko + 2 * tg];

            #pragma unroll
            for (int nt = 0; nt < 4; nt++) {
                mma_tf32(c[0][nt], aA0, aB0, aA4, aB4, b[nt].x, b[nt].y);
                mma_tf32(c[1][nt], aC0, aD0, aC4, aD4, b[nt].x, b[nt].y);
            }
        }

        __syncthreads();   // all warps done reading this B buffer

        // prefetch block it+2 into the buffer just drained (overlaps epilogue)
        if (it < 6) {
            const char* src = (const char*)(g_Wt + (size_t)(it + 2) * 64 * 128);
            uint32_t dst = (it & 1) ? b1_u : b0_u;
            for (int idx = tid; idx < 64 * 32; idx += THREADS) {
                int r = idx >> 5, c16 = (idx & 31) * 16;
                cp_async16(dst + r * (B_ST * 4) + c16, src + r * 512 + c16);
            }
            cp_async_commit();
        }

        // epilogue after second k-half: +bias, leaky-relu, dot with a
        if (kh == 1) {
            #pragma unroll
            for (int mt = 0; mt < 2; mt++) {
                #pragma unroll
                for (int nt = 0; nt < 4; nt++) {
                    int o = nc * 64 + nh * 32 + nt * 8 + 2 * tg;
                    float o20 = o2_s[mw * FF + o];
                    float o21 = o2_s[mw * FF + o + 1];
                    float av0 = a_s[o];
                    float av1 = a_s[o + 1];
                    float y;
                    y = c[mt][nt][0] + o20; y = (y > 0.f) ? y : ALPHA_L * y; ep[mt*2]   += y * av0;
                    y = c[mt][nt][1] + o21; y = (y > 0.f) ? y : ALPHA_L * y; ep[mt*2]   += y * av1;
                    y = c[mt][nt][2] + o20; y = (y > 0.f) ? y : ALPHA_L * y; ep[mt*2+1] += y * av0;
                    y = c[mt][nt][3] + o21; y = (y > 0.f) ? y : ALPHA_L * y; ep[mt*2+1] += y * av1;
                }
            }
        }
    }

    // quad-reduce e partials (cols within quad), publish per n-half
    #pragma unroll
    for (int i = 0; i < 4; i++) {
        ep[i] += __shfl_down_sync(0xffffffffu, ep[i], 2, 4);
        ep[i] += __shfl_down_sync(0xffffffffu, ep[i], 1, 4);
    }
    if (tg == 0) {
        #pragma unroll
        for (int i = 0; i < 4; i++)
            e_sh[nh * 128 + mbase + i * 8 + g] = ep[i];
    }
    __syncthreads();

    // softmax per node (warps 0-3 handle nodes 0-3)
    if (w < 4) {
        float e = e_sh[w * 32 + lane] + e_sh[128 + w * 32 + lane];
        float mx = e;
        #pragma unroll
        for (int o = 16; o > 0; o >>= 1)
            mx = fmaxf(mx, __shfl_xor_sync(0xffffffffu, mx, o));
        float p = expf(e - mx);
        float s = p;
        #pragma unroll
        for (int o = 16; o > 0; o >>= 1)
            s += __shfl_xor_sync(0xffffffffu, s, o);
        float att = p / s;
        att_s[w * 32 + lane] = att;
        out[(size_t)NN * FF + (size_t)(node0 + w) * MMN + lane] = att;
    }
    __syncthreads();

    // h_prime[f] = sum_m att * A (plain smem layout), then ELU
    {
        const int f = tid;
        #pragma unroll
        for (int nl = 0; nl < 4; nl++) {
            float acc = 0.f;
            #pragma unroll 8
            for (int m = 0; m < MMN; m++) {
                int r = nl * MMN + m;
                acc = fmaf(att_s[r], As[r * A_ST + f], acc);
            }
            float rres = (acc > 0.f) ? acc : expm1f(acc);
            out[(size_t)(node0 + nl) * FF + f] = rres;
        }
    }
}

// ---------------------------------------------------------------------------
extern "C" void kernel_launch(void* const* d_in, const int* in_sizes, int n_in,
                              void* d_out, int out_size) {
    const float* transformed = (const float*)d_in[0];
    const float* output      = (const float*)d_in[1];
    const float* W           = (const float*)d_in[2];
    const float* a_vec       = (const float*)d_in[3];
    float* out = (float*)d_out;

    const int smem_o2 = (ROWS_PB * A_STRIDE1 + FF * W_STRIDE1) * sizeof(float);
    cudaFuncSetAttribute(o2_gemm_kernel,
                         cudaFuncAttributeMaxDynamicSharedMemorySize, smem_o2);
    cudaFuncSetAttribute(gat_fused2_kernel,
                         cudaFuncAttributeMaxDynamicSharedMemorySize, GAT_SMEM);

    wt_kernel<<<FF, FF>>>(W);
    o2_gemm_kernel<<<NN / ROWS_PB, THREADS, smem_o2>>>(output, W);
    gat_fused2_kernel<<<NN / 4, THREADS, GAT_SMEM>>>(transformed, a_vec, out);
}

// round 5
// speedup vs baseline: 1.1741x; 1.0070x over previous
#include <cuda_runtime.h>
#include <math.h>
#include <stdint.h>

// Problem constants
#define NN      16384
#define MMN     32
#define FF      256
#define ALPHA_L 0.2f

#define THREADS 256

// ---------------- scratch ----------------
__device__ float g_O2[(size_t)NN * FF];   // output @ W2 (bias per node per out-feat)
// W1 rearranged: 16 blocks [c(4)][q(4)] of [n_local(64)][k_local(64) interleaved]
__device__ float g_Wt[(size_t)FF * FF];

// ---------------- helpers ----------------
__device__ __forceinline__ uint32_t f2tf32(float x) {
    uint32_t r;
    asm("cvt.rna.tf32.f32 %0, %1;" : "=r"(r) : "f"(x));
    return r;
}

__device__ __forceinline__ uint32_t smem_to_u32(const void* p) {
    uint32_t a;
    asm("{ .reg .u64 t; cvta.to.shared.u64 t, %1; cvt.u32.u64 %0, t; }"
        : "=r"(a) : "l"(p));
    return a;
}

__device__ __forceinline__ void cp_async16(uint32_t dst_smem, const void* src) {
    asm volatile("cp.async.cg.shared.global [%0], [%1], 16;"
                 :: "r"(dst_smem), "l"(src) : "memory");
}
__device__ __forceinline__ void cp_async_commit() {
    asm volatile("cp.async.commit_group;" ::: "memory");
}
template <int N>
__device__ __forceinline__ void cp_async_wait() {
    asm volatile("cp.async.wait_group %0;" :: "n"(N) : "memory");
}

__device__ __forceinline__ void mma_tf32(float c[4],
                                         float a0, float a1, float a2, float a3,
                                         float b0, float b1) {
    asm volatile(
        "mma.sync.aligned.m16n8k8.row.col.f32.tf32.tf32.f32 "
        "{%0,%1,%2,%3}, {%4,%5,%6,%7}, {%8,%9}, {%0,%1,%2,%3};\n"
        : "+f"(c[0]), "+f"(c[1]), "+f"(c[2]), "+f"(c[3])
        : "r"(__float_as_uint(a0)), "r"(__float_as_uint(a1)),
          "r"(__float_as_uint(a2)), "r"(__float_as_uint(a3)),
          "r"(__float_as_uint(b0)), "r"(__float_as_uint(b1)));
}

// ---------------------------------------------------------------------------
// Kernel 0: W1 -> g_Wt, tf32-rounded, [c(4)][q(4)][n(64)][k(64) interleaved]
// interleave within 8-block: k -> 2*(k&3) + ((k>>2)&1)
// ---------------------------------------------------------------------------
__global__ void wt_kernel(const float* __restrict__ W) {
    int n = blockIdx.x, k = threadIdx.x;
    int c = n >> 6, nl = n & 63;
    int q = k >> 6, kl = k & 63;
    int pos = (kl & ~7) + 2 * (kl & 3) + ((kl >> 2) & 1);
    size_t dst = ((size_t)((c * 4 + q) * 64 + nl)) * 64 + pos;
    g_Wt[dst] = __uint_as_float(f2tf32(W[(size_t)k * FF + n]));
}

// ---------------------------------------------------------------------------
// Kernel 1: O2 = output @ W2  (round-1 proven kernel, unchanged)
// ---------------------------------------------------------------------------
#define ROWS_PB   128
#define A_STRIDE1 260
#define W_STRIDE1 72

__global__ void __launch_bounds__(THREADS, 1)
o2_gemm_kernel(const float* __restrict__ output, const float* __restrict__ W) {
    extern __shared__ float smemf[];
    float* As = smemf;
    float* Ws = As + ROWS_PB * A_STRIDE1;

    const int tid  = threadIdx.x;
    const int w    = tid >> 5;
    const int lane = tid & 31;
    const int g    = lane >> 2;
    const int tg   = lane & 3;
    const int mbase = w * 16;
    const int row0 = blockIdx.x * ROWS_PB;

    for (int idx = tid; idx < ROWS_PB * (FF / 4); idx += THREADS) {
        int r  = idx >> 6;
        int c4 = (idx & 63) * 4;
        float4 v = *(const float4*)(output + (size_t)(row0 + r) * FF + c4);
        float* d = &As[r * A_STRIDE1 + c4];
        d[0] = __uint_as_float(f2tf32(v.x));
        d[1] = __uint_as_float(f2tf32(v.y));
        d[2] = __uint_as_float(f2tf32(v.z));
        d[3] = __uint_as_float(f2tf32(v.w));
    }

    for (int nc = 0; nc < 4; nc++) {
        __syncthreads();
        for (int idx = tid; idx < FF * 16; idx += THREADS) {
            int k = idx >> 4;
            int j = (idx & 15) * 4;
            float4 v = *(const float4*)(W + (size_t)(FF + k) * FF + nc * 64 + j);
            float* d = &Ws[k * W_STRIDE1 + j];
            d[0] = __uint_as_float(f2tf32(v.x));
            d[1] = __uint_as_float(f2tf32(v.y));
            d[2] = __uint_as_float(f2tf32(v.z));
            d[3] = __uint_as_float(f2tf32(v.w));
        }
        __syncthreads();

        float c[8][4];
        #pragma unroll
        for (int n0 = 0; n0 < 8; n0++)
            #pragma unroll
            for (int i = 0; i < 4; i++) c[n0][i] = 0.f;

        #pragma unroll 4
        for (int k0 = 0; k0 < FF; k0 += 8) {
            float a0 = As[(mbase + g)     * A_STRIDE1 + k0 + tg];
            float a1 = As[(mbase + g + 8) * A_STRIDE1 + k0 + tg];
            float a2 = As[(mbase + g)     * A_STRIDE1 + k0 + tg + 4];
            float a3 = As[(mbase + g + 8) * A_STRIDE1 + k0 + tg + 4];
            #pragma unroll
            for (int n0 = 0; n0 < 8; n0++) {
                float b0 = Ws[(k0 + tg)     * W_STRIDE1 + n0 * 8 + g];
                float b1 = Ws[(k0 + tg + 4) * W_STRIDE1 + n0 * 8 + g];
                mma_tf32(c[n0], a0, a1, a2, a3, b0, b1);
            }
        }

        #pragma unroll
        for (int n0 = 0; n0 < 8; n0++) {
            int col = nc * 64 + n0 * 8 + tg * 2;
            size_t rA = (size_t)(row0 + mbase + g) * FF + col;
            size_t rB = (size_t)(row0 + mbase + g + 8) * FF + col;
            g_O2[rA]     = c[n0][0];
            g_O2[rA + 1] = c[n0][1];
            g_O2[rB]     = c[n0][2];
            g_O2[rB + 1] = c[n0][3];
        }
    }
}

// ---------------------------------------------------------------------------
// Kernel 2: fused GAT. Warp grid 4m x 2chunk, warp tile 32m x 64n.
//   Chunk pairs: pair p covers chunks {2p, 2p+1}; warp (mw, nh) owns chunk 2p+nh.
//   K processed in quarters of 64; B staged per quarter for BOTH chunks,
//   double-buffered via cp.async from pre-arranged g_Wt.
//   A smem: 128 x 260 fp32 (tf32-rounded), plain layout (proven).
//   B smem: 2 dbuf x 2 chunks x (64 n-rows x 64 k, stride 72), k-pair interleaved.
// ---------------------------------------------------------------------------
#define A_ST 260
#define B_ST 72
#define A_BYTES    (128 * A_ST * 4)       // 133120
#define BQ_FLOATS  (64 * B_ST)            // one chunk-quarter: 4608 floats
#define BQ_BYTES   (BQ_FLOATS * 4)        // 18432
#define BITER_FLOATS (2 * BQ_FLOATS)      // both chunks of a pair
#define GAT_SMEM   (A_BYTES + 4 * BQ_BYTES + 4 * FF * 4 + FF * 4 + 128 * 4 + 2 * 128 * 4)

__global__ void __launch_bounds__(THREADS, 1)
gat_fused2_kernel(const float* __restrict__ transformed,
                  const float* __restrict__ a_vec,
                  float* __restrict__ out) {
    extern __shared__ char smem[];
    float* As    = (float*)smem;                               // 128 x 260
    float* Bs    = (float*)(smem + A_BYTES);                   // [2][2][64][72]
    float* o2_s  = (float*)(smem + A_BYTES + 4 * BQ_BYTES);    // 4 x 256
    float* a_s   = o2_s + 4 * FF;                              // 256
    float* att_s = a_s + FF;                                   // 128
    float* e_sh  = att_s + 128;                                // 2 x 128

    const uint32_t bs_u = smem_to_u32(Bs);

    const int tid  = threadIdx.x;
    const int w    = tid >> 5;
    const int lane = tid & 31;
    const int g    = lane >> 2;
    const int tg   = lane & 3;
    const int mw   = w & 3;        // m-warp: rows [mw*32, mw*32+32) -> node mw
    const int nh   = w >> 2;       // chunk-within-pair
    const int mbase = mw * 32;
    const int node0 = blockIdx.x * 4;

    // ---- B fill helper: iteration it = p*4 + q loads blocks (2p, q), (2p+1, q)
    auto fill_b = [&](int it) {
        const int p = it >> 2, q = it & 3;
        const uint32_t dbase = bs_u + (uint32_t)(it & 1) * (2 * BQ_BYTES);
        #pragma unroll
        for (int ch = 0; ch < 2; ch++) {
            const char* src = (const char*)(g_Wt + (size_t)((2 * p + ch) * 4 + q) * 64 * 64);
            const uint32_t dst = dbase + (uint32_t)ch * BQ_BYTES;
            for (int idx = tid; idx < 64 * 16; idx += THREADS) {
                int r = idx >> 4, c16 = (idx & 15) * 16;
                cp_async16(dst + r * (B_ST * 4) + c16, src + r * 256 + c16);
            }
        }
        cp_async_commit();
    };

    // ---- prefetch iterations 0 and 1 ----
    fill_b(0);
    fill_b(1);

    // ---- A tile fill: plain layout, tf32-rounded (proven) ----
    const float* Asrc = transformed + (size_t)(node0 * MMN) * FF;
    for (int idx = tid; idx < 128 * 64; idx += THREADS) {
        int r  = idx >> 6;
        int c4 = (idx & 63) * 4;
        float4 v = *(const float4*)(Asrc + (size_t)r * FF + c4);
        float* d = &As[r * A_ST + c4];
        d[0] = __uint_as_float(f2tf32(v.x));
        d[1] = __uint_as_float(f2tf32(v.y));
        d[2] = __uint_as_float(f2tf32(v.z));
        d[3] = __uint_as_float(f2tf32(v.w));
    }
    // ---- O2 bias + attention vector ----
    for (int idx = tid; idx < 4 * FF; idx += THREADS)
        o2_s[idx] = g_O2[(size_t)(node0 + (idx >> 8)) * FF + (idx & 255)];
    a_s[tid] = a_vec[tid];

    float ep[4] = {0.f, 0.f, 0.f, 0.f};   // e partials: rows mbase+{g,g+8,g+16,g+24}
    float c[2][8][4];                      // 32m x 64n accumulators

    for (int it = 0; it < 8; it++) {       // it = p*4 + q
        const int q = it & 3;

        if (it == 7) cp_async_wait<0>(); else cp_async_wait<1>();
        __syncthreads();

        const float* Bq = Bs + (size_t)(it & 1) * BITER_FLOATS + (size_t)nh * BQ_FLOATS;

        if (q == 0) {
            #pragma unroll
            for (int mt = 0; mt < 2; mt++)
                #pragma unroll
                for (int nt = 0; nt < 8; nt++)
                    #pragma unroll
                    for (int i = 0; i < 4; i++) c[mt][nt][i] = 0.f;
        }

        const int kbase = q * 64;
        #pragma unroll 4
        for (int ko = 0; ko < 64; ko += 8) {
            const int k0 = kbase + ko;
            // A: 8 scalar LDS.32 (conflict-free, banks 4g+tg)
            float aA0 = As[(mbase + g)      * A_ST + k0 + tg];
            float aA4 = As[(mbase + g)      * A_ST + k0 + tg + 4];
            float aB0 = As[(mbase + g + 8)  * A_ST + k0 + tg];
            float aB4 = As[(mbase + g + 8)  * A_ST + k0 + tg + 4];
            float aC0 = As[(mbase + g + 16) * A_ST + k0 + tg];
            float aC4 = As[(mbase + g + 16) * A_ST + k0 + tg + 4];
            float aD0 = As[(mbase + g + 24) * A_ST + k0 + tg];
            float aD4 = As[(mbase + g + 24) * A_ST + k0 + tg + 4];

            #pragma unroll
            for (int nt = 0; nt < 8; nt++) {
                // B: LDS.64, interleaved pair (k0+tg, k0+tg+4) at index ko + 2tg
                float2 b = *(const float2*)&Bq[(nt * 8 + g) * B_ST + ko + 2 * tg];
                mma_tf32(c[0][nt], aA0, aB0, aA4, aB4, b.x, b.y);
                mma_tf32(c[1][nt], aC0, aD0, aC4, aD4, b.x, b.y);
            }
        }

        __syncthreads();   // all warps done reading this B buffer

        // prefetch iteration it+2 into the drained buffer (overlaps epilogue)
        if (it < 6) fill_b(it + 2);

        // epilogue after last quarter of the pair: +bias, lrelu, dot with a
        if (q == 3) {
            const int ch = (it >> 2) * 2 + nh;   // global chunk
            #pragma unroll
            for (int mt = 0; mt < 2; mt++) {
                #pragma unroll
                for (int nt = 0; nt < 8; nt++) {
                    int o = ch * 64 + nt * 8 + 2 * tg;
                    float o20 = o2_s[mw * FF + o];
                    float o21 = o2_s[mw * FF + o + 1];
                    float av0 = a_s[o];
                    float av1 = a_s[o + 1];
                    float y;
                    y = c[mt][nt][0] + o20; y = (y > 0.f) ? y : ALPHA_L * y; ep[mt*2]   += y * av0;
                    y = c[mt][nt][1] + o21; y = (y > 0.f) ? y : ALPHA_L * y; ep[mt*2]   += y * av1;
                    y = c[mt][nt][2] + o20; y = (y > 0.f) ? y : ALPHA_L * y; ep[mt*2+1] += y * av0;
                    y = c[mt][nt][3] + o21; y = (y > 0.f) ? y : ALPHA_L * y; ep[mt*2+1] += y * av1;
                }
            }
        }
    }

    // quad-reduce e partials (cols within quad), publish per chunk-group
    #pragma unroll
    for (int i = 0; i < 4; i++) {
        ep[i] += __shfl_down_sync(0xffffffffu, ep[i], 2, 4);
        ep[i] += __shfl_down_sync(0xffffffffu, ep[i], 1, 4);
    }
    if (tg == 0) {
        #pragma unroll
        for (int i = 0; i < 4; i++)
            e_sh[nh * 128 + mbase + i * 8 + g] = ep[i];
    }
    __syncthreads();

    // softmax per node (warps 0-3 handle nodes 0-3)
    if (w < 4) {
        float e = e_sh[w * 32 + lane] + e_sh[128 + w * 32 + lane];
        float mx = e;
        #pragma unroll
        for (int o = 16; o > 0; o >>= 1)
            mx = fmaxf(mx, __shfl_xor_sync(0xffffffffu, mx, o));
        float p = expf(e - mx);
        float s = p;
        #pragma unroll
        for (int o = 16; o > 0; o >>= 1)
            s += __shfl_xor_sync(0xffffffffu, s, o);
        float att = p / s;
        att_s[w * 32 + lane] = att;
        out[(size_t)NN * FF + (size_t)(node0 + w) * MMN + lane] = att;
    }
    __syncthreads();

    // h_prime[f] = sum_m att * A (plain smem layout), then ELU
    {
        const int f = tid;
        #pragma unroll
        for (int nl = 0; nl < 4; nl++) {
            float acc = 0.f;
            #pragma unroll 8
            for (int m = 0; m < MMN; m++) {
                int r = nl * MMN + m;
                acc = fmaf(att_s[r], As[r * A_ST + f], acc);
            }
            float rres = (acc > 0.f) ? acc : expm1f(acc);
            out[(size_t)(node0 + nl) * FF + f] = rres;
        }
    }
}

// ---------------------------------------------------------------------------
extern "C" void kernel_launch(void* const* d_in, const int* in_sizes, int n_in,
                              void* d_out, int out_size) {
    const float* transformed = (const float*)d_in[0];
    const float* output      = (const float*)d_in[1];
    const float* W           = (const float*)d_in[2];
    const float* a_vec       = (const float*)d_in[3];
    float* out = (float*)d_out;

    const int smem_o2 = (ROWS_PB * A_STRIDE1 + FF * W_STRIDE1) * sizeof(float);
    cudaFuncSetAttribute(o2_gemm_kernel,
                         cudaFuncAttributeMaxDynamicSharedMemorySize, smem_o2);
    cudaFuncSetAttribute(gat_fused2_kernel,
                         cudaFuncAttributeMaxDynamicSharedMemorySize, GAT_SMEM);

    wt_kernel<<<FF, FF>>>(W);
    o2_gemm_kernel<<<NN / ROWS_PB, THREADS, smem_o2>>>(output, W);
    gat_fused2_kernel<<<NN / 4, THREADS, GAT_SMEM>>>(transformed, a_vec, out);
}

// round 6
// speedup vs baseline: 1.1767x; 1.0022x over previous
#include <cuda_runtime.h>
#include <math.h>
#include <stdint.h>

// Problem constants
#define NN      16384
#define MMN     32
#define FF      256
#define ALPHA_L 0.2f

#define THREADS 256

// ---------------- scratch ----------------
__device__ float g_O2[(size_t)NN * FF];   // output @ W2 (bias per node per out-feat)
// W1 rearranged: 16 blocks [c(4)][q(4)] of [n_local(64)][k_local(64) interleaved]
__device__ float g_Wt[(size_t)FF * FF];

// ---------------- helpers ----------------
__device__ __forceinline__ uint32_t f2tf32(float x) {
    uint32_t r;
    asm("cvt.rna.tf32.f32 %0, %1;" : "=r"(r) : "f"(x));
    return r;
}

__device__ __forceinline__ uint32_t smem_to_u32(const void* p) {
    uint32_t a;
    asm("{ .reg .u64 t; cvta.to.shared.u64 t, %1; cvt.u32.u64 %0, t; }"
        : "=r"(a) : "l"(p));
    return a;
}

__device__ __forceinline__ void cp_async16(uint32_t dst_smem, const void* src) {
    asm volatile("cp.async.cg.shared.global [%0], [%1], 16;"
                 :: "r"(dst_smem), "l"(src) : "memory");
}
__device__ __forceinline__ void cp_async_commit() {
    asm volatile("cp.async.commit_group;" ::: "memory");
}
template <int N>
__device__ __forceinline__ void cp_async_wait() {
    asm volatile("cp.async.wait_group %0;" :: "n"(N) : "memory");
}

__device__ __forceinline__ void mma_tf32(float c[4],
                                         float a0, float a1, float a2, float a3,
                                         float b0, float b1) {
    asm volatile(
        "mma.sync.aligned.m16n8k8.row.col.f32.tf32.tf32.f32 "
        "{%0,%1,%2,%3}, {%4,%5,%6,%7}, {%8,%9}, {%0,%1,%2,%3};\n"
        : "+f"(c[0]), "+f"(c[1]), "+f"(c[2]), "+f"(c[3])
        : "r"(__float_as_uint(a0)), "r"(__float_as_uint(a1)),
          "r"(__float_as_uint(a2)), "r"(__float_as_uint(a3)),
          "r"(__float_as_uint(b0)), "r"(__float_as_uint(b1)));
}

// ---------------------------------------------------------------------------
// Kernel 0: W1 -> g_Wt, tf32-rounded, [c(4)][q(4)][n(64)][k(64) interleaved]
// interleave within 8-block: k -> 2*(k&3) + ((k>>2)&1)
// ---------------------------------------------------------------------------
__global__ void wt_kernel(const float* __restrict__ W) {
    int n = blockIdx.x, k = threadIdx.x;
    int c = n >> 6, nl = n & 63;
    int q = k >> 6, kl = k & 63;
    int pos = (kl & ~7) + 2 * (kl & 3) + ((kl >> 2) & 1);
    size_t dst = ((size_t)((c * 4 + q) * 64 + nl)) * 64 + pos;
    g_Wt[dst] = __uint_as_float(f2tf32(W[(size_t)k * FF + n]));
}

// ---------------------------------------------------------------------------
// Kernel 1: O2 = output @ W2  (round-1 proven kernel, unchanged)
// ---------------------------------------------------------------------------
#define ROWS_PB   128
#define A_STRIDE1 260
#define W_STRIDE1 72

__global__ void __launch_bounds__(THREADS, 1)
o2_gemm_kernel(const float* __restrict__ output, const float* __restrict__ W) {
    extern __shared__ float smemf[];
    float* As = smemf;
    float* Ws = As + ROWS_PB * A_STRIDE1;

    const int tid  = threadIdx.x;
    const int w    = tid >> 5;
    const int lane = tid & 31;
    const int g    = lane >> 2;
    const int tg   = lane & 3;
    const int mbase = w * 16;
    const int row0 = blockIdx.x * ROWS_PB;

    for (int idx = tid; idx < ROWS_PB * (FF / 4); idx += THREADS) {
        int r  = idx >> 6;
        int c4 = (idx & 63) * 4;
        float4 v = *(const float4*)(output + (size_t)(row0 + r) * FF + c4);
        float* d = &As[r * A_STRIDE1 + c4];
        d[0] = __uint_as_float(f2tf32(v.x));
        d[1] = __uint_as_float(f2tf32(v.y));
        d[2] = __uint_as_float(f2tf32(v.z));
        d[3] = __uint_as_float(f2tf32(v.w));
    }

    for (int nc = 0; nc < 4; nc++) {
        __syncthreads();
        for (int idx = tid; idx < FF * 16; idx += THREADS) {
            int k = idx >> 4;
            int j = (idx & 15) * 4;
            float4 v = *(const float4*)(W + (size_t)(FF + k) * FF + nc * 64 + j);
            float* d = &Ws[k * W_STRIDE1 + j];
            d[0] = __uint_as_float(f2tf32(v.x));
            d[1] = __uint_as_float(f2tf32(v.y));
            d[2] = __uint_as_float(f2tf32(v.z));
            d[3] = __uint_as_float(f2tf32(v.w));
        }
        __syncthreads();

        float c[8][4];
        #pragma unroll
        for (int n0 = 0; n0 < 8; n0++)
            #pragma unroll
            for (int i = 0; i < 4; i++) c[n0][i] = 0.f;

        #pragma unroll 4
        for (int k0 = 0; k0 < FF; k0 += 8) {
            float a0 = As[(mbase + g)     * A_STRIDE1 + k0 + tg];
            float a1 = As[(mbase + g + 8) * A_STRIDE1 + k0 + tg];
            float a2 = As[(mbase + g)     * A_STRIDE1 + k0 + tg + 4];
            float a3 = As[(mbase + g + 8) * A_STRIDE1 + k0 + tg + 4];
            #pragma unroll
            for (int n0 = 0; n0 < 8; n0++) {
                float b0 = Ws[(k0 + tg)     * W_STRIDE1 + n0 * 8 + g];
                float b1 = Ws[(k0 + tg + 4) * W_STRIDE1 + n0 * 8 + g];
                mma_tf32(c[n0], a0, a1, a2, a3, b0, b1);
            }
        }

        #pragma unroll
        for (int n0 = 0; n0 < 8; n0++) {
            int col = nc * 64 + n0 * 8 + tg * 2;
            size_t rA = (size_t)(row0 + mbase + g) * FF + col;
            size_t rB = (size_t)(row0 + mbase + g + 8) * FF + col;
            g_O2[rA]     = c[n0][0];
            g_O2[rA + 1] = c[n0][1];
            g_O2[rB]     = c[n0][2];
            g_O2[rB + 1] = c[n0][3];
        }
    }
}

// ---------------------------------------------------------------------------
// Kernel 2: fused GAT. Warp grid 4m x 2chunk, warp tile 32m x 64n.
//   Chunk pairs: pair p covers chunks {2p, 2p+1}; warp (mw, nh) owns chunk 2p+nh.
//   K processed in quarters of 64; B staged per quarter for BOTH chunks,
//   double-buffered via cp.async from pre-arranged g_Wt.
//   A smem: 128 x 260 fp32 (tf32-rounded), plain layout (proven).
//   B smem: 2 dbuf x 2 chunks x (64 n-rows x 64 k, stride 72), k-pair interleaved.
// ---------------------------------------------------------------------------
#define A_ST 260
#define B_ST 72
#define A_BYTES    (128 * A_ST * 4)       // 133120
#define BQ_FLOATS  (64 * B_ST)            // one chunk-quarter: 4608 floats
#define BQ_BYTES   (BQ_FLOATS * 4)        // 18432
#define BITER_FLOATS (2 * BQ_FLOATS)      // both chunks of a pair
#define GAT_SMEM   (A_BYTES + 4 * BQ_BYTES + 4 * FF * 4 + FF * 4 + 128 * 4 + 2 * 128 * 4)

__global__ void __launch_bounds__(THREADS, 1)
gat_fused2_kernel(const float* __restrict__ transformed,
                  const float* __restrict__ a_vec,
                  float* __restrict__ out) {
    extern __shared__ char smem[];
    float* As    = (float*)smem;                               // 128 x 260
    float* Bs    = (float*)(smem + A_BYTES);                   // [2][2][64][72]
    float* o2_s  = (float*)(smem + A_BYTES + 4 * BQ_BYTES);    // 4 x 256
    float* a_s   = o2_s + 4 * FF;                              // 256
    float* att_s = a_s + FF;                                   // 128
    float* e_sh  = att_s + 128;                                // 2 x 128

    const uint32_t bs_u = smem_to_u32(Bs);

    const int tid  = threadIdx.x;
    const int w    = tid >> 5;
    const int lane = tid & 31;
    const int g    = lane >> 2;
    const int tg   = lane & 3;
    const int mw   = w & 3;        // m-warp: rows [mw*32, mw*32+32) -> node mw
    const int nh   = w >> 2;       // chunk-within-pair
    const int mbase = mw * 32;
    const int node0 = blockIdx.x * 4;

    // ---- B fill helper: iteration it = p*4 + q loads blocks (2p, q), (2p+1, q)
    auto fill_b = [&](int it) {
        const int p = it >> 2, q = it & 3;
        const uint32_t dbase = bs_u + (uint32_t)(it & 1) * (2 * BQ_BYTES);
        #pragma unroll
        for (int ch = 0; ch < 2; ch++) {
            const char* src = (const char*)(g_Wt + (size_t)((2 * p + ch) * 4 + q) * 64 * 64);
            const uint32_t dst = dbase + (uint32_t)ch * BQ_BYTES;
            for (int idx = tid; idx < 64 * 16; idx += THREADS) {
                int r = idx >> 4, c16 = (idx & 15) * 16;
                cp_async16(dst + r * (B_ST * 4) + c16, src + r * 256 + c16);
            }
        }
        cp_async_commit();
    };

    // ---- prefetch iterations 0 and 1 ----
    fill_b(0);
    fill_b(1);

    // ---- A tile fill: plain layout, tf32-rounded (proven) ----
    const float* Asrc = transformed + (size_t)(node0 * MMN) * FF;
    for (int idx = tid; idx < 128 * 64; idx += THREADS) {
        int r  = idx >> 6;
        int c4 = (idx & 63) * 4;
        float4 v = *(const float4*)(Asrc + (size_t)r * FF + c4);
        float* d = &As[r * A_ST + c4];
        d[0] = __uint_as_float(f2tf32(v.x));
        d[1] = __uint_as_float(f2tf32(v.y));
        d[2] = __uint_as_float(f2tf32(v.z));
        d[3] = __uint_as_float(f2tf32(v.w));
    }
    // ---- O2 bias + attention vector ----
    for (int idx = tid; idx < 4 * FF; idx += THREADS)
        o2_s[idx] = g_O2[(size_t)(node0 + (idx >> 8)) * FF + (idx & 255)];
    a_s[tid] = a_vec[tid];

    float ep[4] = {0.f, 0.f, 0.f, 0.f};   // e partials: rows mbase+{g,g+8,g+16,g+24}
    float c[2][8][4];                      // 32m x 64n accumulators

    for (int it = 0; it < 8; it++) {       // it = p*4 + q
        const int q = it & 3;

        if (it == 7) cp_async_wait<0>(); else cp_async_wait<1>();
        __syncthreads();

        const float* Bq = Bs + (size_t)(it & 1) * BITER_FLOATS + (size_t)nh * BQ_FLOATS;

        if (q == 0) {
            #pragma unroll
            for (int mt = 0; mt < 2; mt++)
                #pragma unroll
                for (int nt = 0; nt < 8; nt++)
                    #pragma unroll
                    for (int i = 0; i < 4; i++) c[mt][nt][i] = 0.f;
        }

        const int kbase = q * 64;
        #pragma unroll 4
        for (int ko = 0; ko < 64; ko += 8) {
            const int k0 = kbase + ko;
            // A: 8 scalar LDS.32 (conflict-free, banks 4g+tg)
            float aA0 = As[(mbase + g)      * A_ST + k0 + tg];
            float aA4 = As[(mbase + g)      * A_ST + k0 + tg + 4];
            float aB0 = As[(mbase + g + 8)  * A_ST + k0 + tg];
            float aB4 = As[(mbase + g + 8)  * A_ST + k0 + tg + 4];
            float aC0 = As[(mbase + g + 16) * A_ST + k0 + tg];
            float aC4 = As[(mbase + g + 16) * A_ST + k0 + tg + 4];
            float aD0 = As[(mbase + g + 24) * A_ST + k0 + tg];
            float aD4 = As[(mbase + g + 24) * A_ST + k0 + tg + 4];

            #pragma unroll
            for (int nt = 0; nt < 8; nt++) {
                // B: LDS.64, interleaved pair (k0+tg, k0+tg+4) at index ko + 2tg
                float2 b = *(const float2*)&Bq[(nt * 8 + g) * B_ST + ko + 2 * tg];
                mma_tf32(c[0][nt], aA0, aB0, aA4, aB4, b.x, b.y);
                mma_tf32(c[1][nt], aC0, aD0, aC4, aD4, b.x, b.y);
            }
        }

        __syncthreads();   // all warps done reading this B buffer

        // prefetch iteration it+2 into the drained buffer (overlaps epilogue)
        if (it < 6) fill_b(it + 2);

        // epilogue after last quarter of the pair: +bias, lrelu, dot with a
        if (q == 3) {
            const int ch = (it >> 2) * 2 + nh;   // global chunk
            #pragma unroll
            for (int mt = 0; mt < 2; mt++) {
                #pragma unroll
                for (int nt = 0; nt < 8; nt++) {
                    int o = ch * 64 + nt * 8 + 2 * tg;
                    float o20 = o2_s[mw * FF + o];
                    float o21 = o2_s[mw * FF + o + 1];
                    float av0 = a_s[o];
                    float av1 = a_s[o + 1];
                    float y;
                    y = c[mt][nt][0] + o20; y = (y > 0.f) ? y : ALPHA_L * y; ep[mt*2]   += y * av0;
                    y = c[mt][nt][1] + o21; y = (y > 0.f) ? y : ALPHA_L * y; ep[mt*2]   += y * av1;
                    y = c[mt][nt][2] + o20; y = (y > 0.f) ? y : ALPHA_L * y; ep[mt*2+1] += y * av0;
                    y = c[mt][nt][3] + o21; y = (y > 0.f) ? y : ALPHA_L * y; ep[mt*2+1] += y * av1;
                }
            }
        }
    }

    // quad-reduce e partials (cols within quad), publish per chunk-group
    #pragma unroll
    for (int i = 0; i < 4; i++) {
        ep[i] += __shfl_down_sync(0xffffffffu, ep[i], 2, 4);
        ep[i] += __shfl_down_sync(0xffffffffu, ep[i], 1, 4);
    }
    if (tg == 0) {
        #pragma unroll
        for (int i = 0; i < 4; i++)
            e_sh[nh * 128 + mbase + i * 8 + g] = ep[i];
    }
    __syncthreads();

    // softmax per node (warps 0-3 handle nodes 0-3)
    if (w < 4) {
        float e = e_sh[w * 32 + lane] + e_sh[128 + w * 32 + lane];
        float mx = e;
        #pragma unroll
        for (int o = 16; o > 0; o >>= 1)
            mx = fmaxf(mx, __shfl_xor_sync(0xffffffffu, mx, o));
        float p = expf(e - mx);
        float s = p;
        #pragma unroll
        for (int o = 16; o > 0; o >>= 1)
            s += __shfl_xor_sync(0xffffffffu, s, o);
        float att = p / s;
        att_s[w * 32 + lane] = att;
        out[(size_t)NN * FF + (size_t)(node0 + w) * MMN + lane] = att;
    }
    __syncthreads();

    // h_prime[f] = sum_m att * A (plain smem layout), then ELU
    {
        const int f = tid;
        #pragma unroll
        for (int nl = 0; nl < 4; nl++) {
            float acc = 0.f;
            #pragma unroll 8
            for (int m = 0; m < MMN; m++) {
                int r = nl * MMN + m;
                acc = fmaf(att_s[r], As[r * A_ST + f], acc);
            }
            float rres = (acc > 0.f) ? acc : expm1f(acc);
            out[(size_t)(node0 + nl) * FF + f] = rres;
        }
    }
}

// ---------------------------------------------------------------------------
extern "C" void kernel_launch(void* const* d_in, const int* in_sizes, int n_in,
                              void* d_out, int out_size) {
    const float* transformed = (const float*)d_in[0];
    const float* output      = (const float*)d_in[1];
    const float* W           = (const float*)d_in[2];
    const float* a_vec       = (const float*)d_in[3];
    float* out = (float*)d_out;

    const int smem_o2 = (ROWS_PB * A_STRIDE1 + FF * W_STRIDE1) * sizeof(float);
    cudaFuncSetAttribute(o2_gemm_kernel,
                         cudaFuncAttributeMaxDynamicSharedMemorySize, smem_o2);
    cudaFuncSetAttribute(gat_fused2_kernel,
                         cudaFuncAttributeMaxDynamicSharedMemorySize, GAT_SMEM);

    wt_kernel<<<FF, FF>>>(W);
    o2_gemm_kernel<<<NN / ROWS_PB, THREADS, smem_o2>>>(output, W);
    gat_fused2_kernel<<<NN / 4, THREADS, GAT_SMEM>>>(transformed, a_vec, out);
}

// round 7
// speedup vs baseline: 1.1775x; 1.0007x over previous
#include <cuda_runtime.h>
#include <math.h>
#include <stdint.h>

// Problem constants
#define NN      16384
#define MMN     32
#define FF      256
#define ALPHA_L 0.2f

#define THREADS 256

// ---------------- scratch ----------------
__device__ float g_O2[(size_t)NN * FF];   // output @ W2 (bias per node per out-feat)
// W1 rearranged: 16 blocks [c(4)][q(4)] of [n_local(64)][k_local(64) interleaved]
__device__ float g_Wt[(size_t)FF * FF];

// ---------------- helpers ----------------
__device__ __forceinline__ uint32_t f2tf32(float x) {
    uint32_t r;
    asm("cvt.rna.tf32.f32 %0, %1;" : "=r"(r) : "f"(x));
    return r;
}

__device__ __forceinline__ uint32_t smem_to_u32(const void* p) {
    uint32_t a;
    asm("{ .reg .u64 t; cvta.to.shared.u64 t, %1; cvt.u32.u64 %0, t; }"
        : "=r"(a) : "l"(p));
    return a;
}

__device__ __forceinline__ void cp_async16(uint32_t dst_smem, const void* src) {
    asm volatile("cp.async.cg.shared.global [%0], [%1], 16;"
                 :: "r"(dst_smem), "l"(src) : "memory");
}
__device__ __forceinline__ void cp_async_commit() {
    asm volatile("cp.async.commit_group;" ::: "memory");
}
template <int N>
__device__ __forceinline__ void cp_async_wait() {
    asm volatile("cp.async.wait_group %0;" :: "n"(N) : "memory");
}

__device__ __forceinline__ void mma_tf32(float c[4],
                                         float a0, float a1, float a2, float a3,
                                         float b0, float b1) {
    asm volatile(
        "mma.sync.aligned.m16n8k8.row.col.f32.tf32.tf32.f32 "
        "{%0,%1,%2,%3}, {%4,%5,%6,%7}, {%8,%9}, {%0,%1,%2,%3};\n"
        : "+f"(c[0]), "+f"(c[1]), "+f"(c[2]), "+f"(c[3])
        : "r"(__float_as_uint(a0)), "r"(__float_as_uint(a1)),
          "r"(__float_as_uint(a2)), "r"(__float_as_uint(a3)),
          "r"(__float_as_uint(b0)), "r"(__float_as_uint(b1)));
}

// ---------------------------------------------------------------------------
// Kernel 0: W1 -> g_Wt, tf32-rounded, [c(4)][q(4)][n(64)][k(64) interleaved]
// interleave within 8-block: k -> 2*(k&3) + ((k>>2)&1)
// ---------------------------------------------------------------------------
__global__ void wt_kernel(const float* __restrict__ W) {
    int n = blockIdx.x, k = threadIdx.x;
    int c = n >> 6, nl = n & 63;
    int q = k >> 6, kl = k & 63;
    int pos = (kl & ~7) + 2 * (kl & 3) + ((kl >> 2) & 1);
    size_t dst = ((size_t)((c * 4 + q) * 64 + nl)) * 64 + pos;
    g_Wt[dst] = __uint_as_float(f2tf32(W[(size_t)k * FF + n]));
}

// ---------------------------------------------------------------------------
// Kernel 1: O2 = output @ W2  (round-1 proven kernel, unchanged)
// ---------------------------------------------------------------------------
#define ROWS_PB   128
#define A_STRIDE1 260
#define W_STRIDE1 72

__global__ void __launch_bounds__(THREADS, 1)
o2_gemm_kernel(const float* __restrict__ output, const float* __restrict__ W) {
    extern __shared__ float smemf[];
    float* As = smemf;
    float* Ws = As + ROWS_PB * A_STRIDE1;

    const int tid  = threadIdx.x;
    const int w    = tid >> 5;
    const int lane = tid & 31;
    const int g    = lane >> 2;
    const int tg   = lane & 3;
    const int mbase = w * 16;
    const int row0 = blockIdx.x * ROWS_PB;

    for (int idx = tid; idx < ROWS_PB * (FF / 4); idx += THREADS) {
        int r  = idx >> 6;
        int c4 = (idx & 63) * 4;
        float4 v = *(const float4*)(output + (size_t)(row0 + r) * FF + c4);
        float* d = &As[r * A_STRIDE1 + c4];
        d[0] = __uint_as_float(f2tf32(v.x));
        d[1] = __uint_as_float(f2tf32(v.y));
        d[2] = __uint_as_float(f2tf32(v.z));
        d[3] = __uint_as_float(f2tf32(v.w));
    }

    for (int nc = 0; nc < 4; nc++) {
        __syncthreads();
        for (int idx = tid; idx < FF * 16; idx += THREADS) {
            int k = idx >> 4;
            int j = (idx & 15) * 4;
            float4 v = *(const float4*)(W + (size_t)(FF + k) * FF + nc * 64 + j);
            float* d = &Ws[k * W_STRIDE1 + j];
            d[0] = __uint_as_float(f2tf32(v.x));
            d[1] = __uint_as_float(f2tf32(v.y));
            d[2] = __uint_as_float(f2tf32(v.z));
            d[3] = __uint_as_float(f2tf32(v.w));
        }
        __syncthreads();

        float c[8][4];
        #pragma unroll
        for (int n0 = 0; n0 < 8; n0++)
            #pragma unroll
            for (int i = 0; i < 4; i++) c[n0][i] = 0.f;

        #pragma unroll 4
        for (int k0 = 0; k0 < FF; k0 += 8) {
            float a0 = As[(mbase + g)     * A_STRIDE1 + k0 + tg];
            float a1 = As[(mbase + g + 8) * A_STRIDE1 + k0 + tg];
            float a2 = As[(mbase + g)     * A_STRIDE1 + k0 + tg + 4];
            float a3 = As[(mbase + g + 8) * A_STRIDE1 + k0 + tg + 4];
            #pragma unroll
            for (int n0 = 0; n0 < 8; n0++) {
                float b0 = Ws[(k0 + tg)     * W_STRIDE1 + n0 * 8 + g];
                float b1 = Ws[(k0 + tg + 4) * W_STRIDE1 + n0 * 8 + g];
                mma_tf32(c[n0], a0, a1, a2, a3, b0, b1);
            }
        }

        #pragma unroll
        for (int n0 = 0; n0 < 8; n0++) {
            int col = nc * 64 + n0 * 8 + tg * 2;
            size_t rA = (size_t)(row0 + mbase + g) * FF + col;
            size_t rB = (size_t)(row0 + mbase + g + 8) * FF + col;
            g_O2[rA]     = c[n0][0];
            g_O2[rA + 1] = c[n0][1];
            g_O2[rB]     = c[n0][2];
            g_O2[rB + 1] = c[n0][3];
        }
    }
}

// ---------------------------------------------------------------------------
// Kernel 2: fused GAT. Warp grid 4m x 2chunk, warp tile 32m x 64n.
//   Chunk pairs: pair p covers chunks {2p, 2p+1}; warp (mw, nh) owns chunk 2p+nh.
//   K processed in quarters of 64; B staged per quarter for BOTH chunks,
//   double-buffered via cp.async from pre-arranged g_Wt.
//   A smem: 128 x 260 fp32 (tf32-rounded), plain layout (proven).
//   B smem: 2 dbuf x 2 chunks x (64 n-rows x 64 k, stride 72), k-pair interleaved.
// ---------------------------------------------------------------------------
#define A_ST 260
#define B_ST 72
#define A_BYTES    (128 * A_ST * 4)       // 133120
#define BQ_FLOATS  (64 * B_ST)            // one chunk-quarter: 4608 floats
#define BQ_BYTES   (BQ_FLOATS * 4)        // 18432
#define BITER_FLOATS (2 * BQ_FLOATS)      // both chunks of a pair
#define GAT_SMEM   (A_BYTES + 4 * BQ_BYTES + 4 * FF * 4 + FF * 4 + 128 * 4 + 2 * 128 * 4)

__global__ void __launch_bounds__(THREADS, 1)
gat_fused2_kernel(const float* __restrict__ transformed,
                  const float* __restrict__ a_vec,
                  float* __restrict__ out) {
    extern __shared__ char smem[];
    float* As    = (float*)smem;                               // 128 x 260
    float* Bs    = (float*)(smem + A_BYTES);                   // [2][2][64][72]
    float* o2_s  = (float*)(smem + A_BYTES + 4 * BQ_BYTES);    // 4 x 256
    float* a_s   = o2_s + 4 * FF;                              // 256
    float* att_s = a_s + FF;                                   // 128
    float* e_sh  = att_s + 128;                                // 2 x 128

    const uint32_t bs_u = smem_to_u32(Bs);

    const int tid  = threadIdx.x;
    const int w    = tid >> 5;
    const int lane = tid & 31;
    const int g    = lane >> 2;
    const int tg   = lane & 3;
    const int mw   = w & 3;        // m-warp: rows [mw*32, mw*32+32) -> node mw
    const int nh   = w >> 2;       // chunk-within-pair
    const int mbase = mw * 32;
    const int node0 = blockIdx.x * 4;

    // ---- B fill helper: iteration it = p*4 + q loads blocks (2p, q), (2p+1, q)
    auto fill_b = [&](int it) {
        const int p = it >> 2, q = it & 3;
        const uint32_t dbase = bs_u + (uint32_t)(it & 1) * (2 * BQ_BYTES);
        #pragma unroll
        for (int ch = 0; ch < 2; ch++) {
            const char* src = (const char*)(g_Wt + (size_t)((2 * p + ch) * 4 + q) * 64 * 64);
            const uint32_t dst = dbase + (uint32_t)ch * BQ_BYTES;
            for (int idx = tid; idx < 64 * 16; idx += THREADS) {
                int r = idx >> 4, c16 = (idx & 15) * 16;
                cp_async16(dst + r * (B_ST * 4) + c16, src + r * 256 + c16);
            }
        }
        cp_async_commit();
    };

    // ---- prefetch iterations 0 and 1 ----
    fill_b(0);
    fill_b(1);

    // ---- A tile fill: plain layout, tf32-rounded (proven) ----
    const float* Asrc = transformed + (size_t)(node0 * MMN) * FF;
    for (int idx = tid; idx < 128 * 64; idx += THREADS) {
        int r  = idx >> 6;
        int c4 = (idx & 63) * 4;
        float4 v = *(const float4*)(Asrc + (size_t)r * FF + c4);
        float* d = &As[r * A_ST + c4];
        d[0] = __uint_as_float(f2tf32(v.x));
        d[1] = __uint_as_float(f2tf32(v.y));
        d[2] = __uint_as_float(f2tf32(v.z));
        d[3] = __uint_as_float(f2tf32(v.w));
    }
    // ---- O2 bias + attention vector ----
    for (int idx = tid; idx < 4 * FF; idx += THREADS)
        o2_s[idx] = g_O2[(size_t)(node0 + (idx >> 8)) * FF + (idx & 255)];
    a_s[tid] = a_vec[tid];

    float ep[4] = {0.f, 0.f, 0.f, 0.f};   // e partials: rows mbase+{g,g+8,g+16,g+24}
    float c[2][8][4];                      // 32m x 64n accumulators

    for (int it = 0; it < 8; it++) {       // it = p*4 + q
        const int q = it & 3;

        if (it == 7) cp_async_wait<0>(); else cp_async_wait<1>();
        __syncthreads();

        const float* Bq = Bs + (size_t)(it & 1) * BITER_FLOATS + (size_t)nh * BQ_FLOATS;

        if (q == 0) {
            #pragma unroll
            for (int mt = 0; mt < 2; mt++)
                #pragma unroll
                for (int nt = 0; nt < 8; nt++)
                    #pragma unroll
                    for (int i = 0; i < 4; i++) c[mt][nt][i] = 0.f;
        }

        const int kbase = q * 64;
        #pragma unroll 4
        for (int ko = 0; ko < 64; ko += 8) {
            const int k0 = kbase + ko;
            // A: 8 scalar LDS.32 (conflict-free, banks 4g+tg)
            float aA0 = As[(mbase + g)      * A_ST + k0 + tg];
            float aA4 = As[(mbase + g)      * A_ST + k0 + tg + 4];
            float aB0 = As[(mbase + g + 8)  * A_ST + k0 + tg];
            float aB4 = As[(mbase + g + 8)  * A_ST + k0 + tg + 4];
            float aC0 = As[(mbase + g + 16) * A_ST + k0 + tg];
            float aC4 = As[(mbase + g + 16) * A_ST + k0 + tg + 4];
            float aD0 = As[(mbase + g + 24) * A_ST + k0 + tg];
            float aD4 = As[(mbase + g + 24) * A_ST + k0 + tg + 4];

            #pragma unroll
            for (int nt = 0; nt < 8; nt++) {
                // B: LDS.64, interleaved pair (k0+tg, k0+tg+4) at index ko + 2tg
                float2 b = *(const float2*)&Bq[(nt * 8 + g) * B_ST + ko + 2 * tg];
                mma_tf32(c[0][nt], aA0, aB0, aA4, aB4, b.x, b.y);
                mma_tf32(c[1][nt], aC0, aD0, aC4, aD4, b.x, b.y);
            }
        }

        __syncthreads();   // all warps done reading this B buffer

        // prefetch iteration it+2 into the drained buffer (overlaps epilogue)
        if (it < 6) fill_b(it + 2);

        // epilogue after last quarter of the pair: +bias, lrelu, dot with a
        if (q == 3) {
            const int ch = (it >> 2) * 2 + nh;   // global chunk
            #pragma unroll
            for (int mt = 0; mt < 2; mt++) {
                #pragma unroll
                for (int nt = 0; nt < 8; nt++) {
                    int o = ch * 64 + nt * 8 + 2 * tg;
                    float o20 = o2_s[mw * FF + o];
                    float o21 = o2_s[mw * FF + o + 1];
                    float av0 = a_s[o];
                    float av1 = a_s[o + 1];
                    float y;
                    y = c[mt][nt][0] + o20; y = (y > 0.f) ? y : ALPHA_L * y; ep[mt*2]   += y * av0;
                    y = c[mt][nt][1] + o21; y = (y > 0.f) ? y : ALPHA_L * y; ep[mt*2]   += y * av1;
                    y = c[mt][nt][2] + o20; y = (y > 0.f) ? y : ALPHA_L * y; ep[mt*2+1] += y * av0;
                    y = c[mt][nt][3] + o21; y = (y > 0.f) ? y : ALPHA_L * y; ep[mt*2+1] += y * av1;
                }
            }
        }
    }

    // quad-reduce e partials (cols within quad), publish per chunk-group
    #pragma unroll
    for (int i = 0; i < 4; i++) {
        ep[i] += __shfl_down_sync(0xffffffffu, ep[i], 2, 4);
        ep[i] += __shfl_down_sync(0xffffffffu, ep[i], 1, 4);
    }
    if (tg == 0) {
        #pragma unroll
        for (int i = 0; i < 4; i++)
            e_sh[nh * 128 + mbase + i * 8 + g] = ep[i];
    }
    __syncthreads();

    // softmax per node (warps 0-3 handle nodes 0-3)
    if (w < 4) {
        float e = e_sh[w * 32 + lane] + e_sh[128 + w * 32 + lane];
        float mx = e;
        #pragma unroll
        for (int o = 16; o > 0; o >>= 1)
            mx = fmaxf(mx, __shfl_xor_sync(0xffffffffu, mx, o));
        float p = expf(e - mx);
        float s = p;
        #pragma unroll
        for (int o = 16; o > 0; o >>= 1)
            s += __shfl_xor_sync(0xffffffffu, s, o);
        float att = p / s;
        att_s[w * 32 + lane] = att;
        out[(size_t)NN * FF + (size_t)(node0 + w) * MMN + lane] = att;
    }
    __syncthreads();

    // h_prime[f] = sum_m att * A (plain smem layout), then ELU
    {
        const int f = tid;
        #pragma unroll
        for (int nl = 0; nl < 4; nl++) {
            float acc = 0.f;
            #pragma unroll 8
            for (int m = 0; m < MMN; m++) {
                int r = nl * MMN + m;
                acc = fmaf(att_s[r], As[r * A_ST + f], acc);
            }
            float rres = (acc > 0.f) ? acc : expm1f(acc);
            out[(size_t)(node0 + nl) * FF + f] = rres;
        }
    }
}

// ---------------------------------------------------------------------------
extern "C" void kernel_launch(void* const* d_in, const int* in_sizes, int n_in,
                              void* d_out, int out_size) {
    const float* transformed = (const float*)d_in[0];
    const float* output      = (const float*)d_in[1];
    const float* W           = (const float*)d_in[2];
    const float* a_vec       = (const float*)d_in[3];
    float* out = (float*)d_out;

    const int smem_o2 = (ROWS_PB * A_STRIDE1 + FF * W_STRIDE1) * sizeof(float);
    cudaFuncSetAttribute(o2_gemm_kernel,
                         cudaFuncAttributeMaxDynamicSharedMemorySize, smem_o2);
    cudaFuncSetAttribute(gat_fused2_kernel,
                         cudaFuncAttributeMaxDynamicSharedMemorySize, GAT_SMEM);

    wt_kernel<<<FF, FF>>>(W);
    o2_gemm_kernel<<<NN / ROWS_PB, THREADS, smem_o2>>>(output, W);
    gat_fused2_kernel<<<NN / 4, THREADS, GAT_SMEM>>>(transformed, a_vec, out);
}